// round 9
// baseline (speedup 1.0000x reference)
#include <cuda_runtime.h>
#include <cuda_bf16.h>

// End2EndRVFixedOutput_TRT fixed-output ragged copy.
// Inputs (metadata order):
//   d_in[0] = num_dets : int32 [B]          (B = 8, values in [0, 12))
//   d_in[1] = boxes    : float32 [B, N, 4]  (N = 8192)
//   d_in[2] = scores   : float32 [B, N]
//   d_in[3] = classes  : float32 [B, N]
// Output: float32 [100, 7], columns = [batch_id, box0..3, class, score]
//
// Semantics: for n = 0..B-1 in order (later overwrites earlier):
//   off = (n == 0) ? 0 : num_dets[n-1];  k = num_dets[n]
//   out[off : off+k] = [n, boxes[n,0:k], classes[n,0:k], scores[n,0:k]]
// Uncovered rows are zero. Equivalently: largest covering n wins; else 0.
//
// Design:
//  - Single exposed DRAM latency: all candidate source data (num_dets < 12
//    => src <= 10) is prefetched into shared in parallel with num_dets.
//  - Vectorized output: 700 floats = 175 aligned float4s. 192 threads
//    (6 warps), one STG.128 per thread. Rows >= 22 are provably zero, so
//    float4 indices 39..174 are stored pre-barrier, overlapped with the
//    in-flight prefetch loads.

#define OUT_ROWS 100
#define OUT_COLS 7
#define NB 8                       // batch count (fixed by problem shape)
#define KMAX 11                    // num_dets < 12  =>  src <= 10
#define OUT_ELEMS (OUT_ROWS * OUT_COLS)   // 700
#define OUT_VEC4  (OUT_ELEMS / 4)         // 175 float4 stores
#define LIVE_VEC4 39               // float4 idx < 39 may contain live elements
                                   // (elements < 156 ⊇ live rows 0..21 = elems < 154)
#define NTHREADS 192               // 6 warps; covers 184 prefetch slots

__global__ void __launch_bounds__(NTHREADS, 1)
e2e_fixed_output_kernel(const int* __restrict__ num_dets,
                        const float* __restrict__ boxes,
                        const float* __restrict__ scores,
                        const float* __restrict__ classes,
                        float4* __restrict__ out4,
                        int N) {
    __shared__ int    s_nd[NB];
    __shared__ float4 s_box[NB * KMAX];   // boxes[n, src, 0:4]
    __shared__ float  s_cls[NB * KMAX];   // classes[n, src]
    __shared__ float  s_scr[NB * KMAX];   // scores[n, src]

    const int t = threadIdx.x;

    // ---- Phase 1a: issue all prefetch loads (independent, high MLP) ----
    if (t < NB) {
        s_nd[t] = num_dets[t];
    } else if (t < NB + NB * KMAX) {
        int i = t - NB;                                   // 0..87
        int n = i / KMAX, src = i % KMAX;
        s_box[i] = *reinterpret_cast<const float4*>(boxes + ((size_t)n * N + src) * 4);
    } else if (t < NB + 2 * NB * KMAX) {                  // t in [96, 184)
        int i = t - (NB + NB * KMAX);
        int n = i / KMAX, src = i % KMAX;
        s_cls[i] = classes[(size_t)n * N + src];
        s_scr[i] = scores[(size_t)n * N + src];
    }

    // ---- Phase 1b: all-zero float4s stored pre-barrier (no dependency on
    //      the loads above; overlaps their DRAM latency). idx 39..174. ----
    const float4 z4 = make_float4(0.f, 0.f, 0.f, 0.f);
    if (t < OUT_VEC4 - LIVE_VEC4)                         // t in [0, 136)
        out4[LIVE_VEC4 + t] = z4;

    __syncthreads();

    // ---- Phase 2: resolve live float4s (idx 0..38) from shared ----
    if (t >= LIVE_VEC4) return;

    float v[4];
    #pragma unroll
    for (int j = 0; j < 4; ++j) {
        const int e = 4 * t + j;          // element index 0..155
        const int r = e / OUT_COLS;       // row 0..22
        const int c = e % OUT_COLS;

        float val = 0.0f;
        // Largest covering n wins (later batches overwrite earlier rows).
        #pragma unroll
        for (int n = NB - 1; n >= 0; --n) {
            const int off = (n == 0) ? 0 : s_nd[n - 1];
            const int k   = s_nd[n];
            if (r >= off && r < off + k) {
                const int src = r - off;  // < k <= KMAX, in-bounds by mask
                const int i   = n * KMAX + src;
                if (c == 0)      val = (float)n;
                else if (c <= 4) val = (&s_box[i].x)[c - 1];
                else if (c == 5) val = s_cls[i];
                else             val = s_scr[i];
                break;
            }
        }
        v[j] = val;
    }
    out4[t] = make_float4(v[0], v[1], v[2], v[3]);
}

extern "C" void kernel_launch(void* const* d_in, const int* in_sizes, int n_in,
                              void* d_out, int out_size) {
    const int*   num_dets = (const int*)d_in[0];
    const float* boxes    = (const float*)d_in[1];
    const float* scores   = (const float*)d_in[2];
    const float* classes  = (const float*)d_in[3];
    float4*      out4     = (float4*)d_out;

    const int B = in_sizes[0];          // 8
    const int N = in_sizes[2] / B;      // 8192

    e2e_fixed_output_kernel<<<1, NTHREADS>>>(num_dets, boxes, scores, classes, out4, N);
}

// round 10
// speedup vs baseline: 1.0385x; 1.0385x over previous
#include <cuda_runtime.h>
#include <cuda_bf16.h>

// End2EndRVFixedOutput_TRT fixed-output ragged copy.
// Inputs (metadata order):
//   d_in[0] = num_dets : int32 [B]          (B = 8, values in [0, 12))
//   d_in[1] = boxes    : float32 [B, N, 4]  (N = 8192)
//   d_in[2] = scores   : float32 [B, N]
//   d_in[3] = classes  : float32 [B, N]
// Output: float32 [100, 7], columns = [batch_id, box0..3, class, score]
//
// Semantics: for n = 0..B-1 in order (later overwrites earlier):
//   off = (n == 0) ? 0 : num_dets[n-1];  k = num_dets[n]
//   out[off : off+k] = [n, boxes[n,0:k], classes[n,0:k], scores[n,0:k]]
// Uncovered rows are zero. Equivalently: largest covering n wins; else 0.
//
// Design (barrier-free): inputs are resident in L2 across graph replays
// (~3 MB vs 126 MB L2), so a dependent 2-load chain costs ~2 x L2-hit
// latency with NO __syncthreads, NO shared memory, NO LDS round trips:
//   LDG(num_dets as 2x int4, uniform addr -> broadcast)
//     -> unrolled covering-batch scan in registers
//     -> one dependent data LDG -> STG.
// Rows >= 22 are provably zero (off <= 11, k <= 11): those 546 threads issue
// a single zero STG and retire immediately (17 of 22 warps exit in ~20 cyc).

#define OUT_ROWS 100
#define OUT_COLS 7
#define NB 8
#define LIVE_ELEMS (22 * OUT_COLS)          // 154
#define NTHREADS (OUT_ROWS * OUT_COLS + 4)  // 704 = 22 full warps

__global__ void __launch_bounds__(NTHREADS, 1)
e2e_fixed_output_kernel(const int4* __restrict__ num_dets4,
                        const float* __restrict__ boxes,
                        const float* __restrict__ scores,
                        const float* __restrict__ classes,
                        float* __restrict__ out,
                        int N) {
    const int t = threadIdx.x;
    if (t >= OUT_ROWS * OUT_COLS) return;

    // Fast path: provably-zero elements store and retire immediately.
    if (t >= LIVE_ELEMS) {
        out[t] = 0.0f;
        return;
    }

    // All 8 num_dets in registers via two uniform-address vector loads
    // (single L1tex wavefront each; L2-resident across replays).
    const int4 lo = num_dets4[0];   // nd[0..3]
    const int4 hi = num_dets4[1];   // nd[4..7]
    const int nd[NB] = {lo.x, lo.y, lo.z, lo.w, hi.x, hi.y, hi.z, hi.w};

    const int r = t / OUT_COLS;     // 0..21
    const int c = t % OUT_COLS;

    // Largest covering n wins (later batches overwrite earlier rows).
    // Fully unrolled: nd[] indices are compile-time constants -> registers.
    int hit_n = -1, hit_src = 0;
    #pragma unroll
    for (int n = NB - 1; n >= 0; --n) {
        const int off = (n == 0) ? 0 : nd[n - 1];
        const int k   = nd[n];
        if (hit_n < 0 && r >= off && r < off + k) {
            hit_n = n;
            hit_src = r - off;
        }
    }

    float val = 0.0f;
    if (hit_n >= 0) {
        const size_t base = (size_t)hit_n * N + hit_src;
        if (c == 0)      val = (float)hit_n;
        else if (c <= 4) val = boxes[base * 4 + (c - 1)];
        else if (c == 5) val = classes[base];
        else             val = scores[base];
    }
    out[t] = val;
}

extern "C" void kernel_launch(void* const* d_in, const int* in_sizes, int n_in,
                              void* d_out, int out_size) {
    const int4*  num_dets4 = (const int4*)d_in[0];
    const float* boxes     = (const float*)d_in[1];
    const float* scores    = (const float*)d_in[2];
    const float* classes   = (const float*)d_in[3];
    float*       out       = (float*)d_out;

    const int B = in_sizes[0];          // 8
    const int N = in_sizes[2] / B;      // 8192

    e2e_fixed_output_kernel<<<1, NTHREADS>>>(num_dets4, boxes, scores, classes, out, N);
}

// round 11
// speedup vs baseline: 1.5105x; 1.4545x over previous
#include <cuda_runtime.h>
#include <cuda_bf16.h>

// End2EndRVFixedOutput_TRT fixed-output ragged copy.
// Inputs (metadata order):
//   d_in[0] = num_dets : int32 [B]          (B = 8, values in [0, 12))
//   d_in[1] = boxes    : float32 [B, N, 4]  (N = 8192)
//   d_in[2] = scores   : float32 [B, N]
//   d_in[3] = classes  : float32 [B, N]
// Output: float32 [100, 7], columns = [batch_id, box0..3, class, score]
//
// Semantics: for n = 0..B-1 in order (later overwrites earlier):
//   off = (n == 0) ? 0 : num_dets[n-1];  k = num_dets[n]
//   out[off : off+k] = [n, boxes[n,0:k], classes[n,0:k], scores[n,0:k]]
// Uncovered rows are zero. Equivalently: largest covering n wins; else 0.
//
// Design (barrier-free + minimal footprint):
//  - Inputs are L2-resident across graph replays (~3 MB vs 126 MB L2), so the
//    live path is a dependent 2 x L2-hit chain with NO __syncthreads and NO
//    shared memory: uniform int4 LDG of num_dets (broadcast) -> register scan
//    -> one dependent data LDG -> STG.  (Best measured kernel dur: 4.35 us.)
//  - Rows >= 22 are provably zero (off <= 11, k <= 11). The 546-element zero
//    region is written as 2 scalar + 136 float4 stores, issued independently
//    of (and overlapped with) the live path's loads.
//  - 192 threads / 6 warps total.

#define OUT_ROWS 100
#define OUT_COLS 7
#define NB 8
#define OUT_ELEMS  (OUT_ROWS * OUT_COLS)   // 700
#define LIVE_ELEMS (22 * OUT_COLS)         // 154: only rows < 22 can be nonzero
#define ZV4_FIRST  39                      // first 16B-aligned float4 in zero region (elem 156)
#define ZV4_COUNT  136                     // float4s covering elems 156..699
#define NTHREADS 192                       // 6 warps

__global__ void __launch_bounds__(NTHREADS, 1)
e2e_fixed_output_kernel(const int4* __restrict__ num_dets4,
                        const float* __restrict__ boxes,
                        const float* __restrict__ scores,
                        const float* __restrict__ classes,
                        float* __restrict__ out,
                        int N) {
    const int t = threadIdx.x;

    // ---- Zero region: independent stores, overlap the live path's loads ----
    // Elems 154, 155 (unaligned head) by threads 154, 155:
    if (t == 154 || t == 155)
        out[t] = 0.0f;
    // Elems 156..699 as 136 aligned float4 stores by threads 0..135:
    if (t < ZV4_COUNT)
        reinterpret_cast<float4*>(out)[ZV4_FIRST + t] =
            make_float4(0.f, 0.f, 0.f, 0.f);

    if (t >= LIVE_ELEMS) return;

    // ---- Live path: all 8 num_dets via two uniform-address vector loads ----
    const int4 lo = num_dets4[0];   // nd[0..3]
    const int4 hi = num_dets4[1];   // nd[4..7]
    const int nd[NB] = {lo.x, lo.y, lo.z, lo.w, hi.x, hi.y, hi.z, hi.w};

    const int r = t / OUT_COLS;     // 0..21
    const int c = t % OUT_COLS;

    // Largest covering n wins (later batches overwrite earlier rows).
    // Fully unrolled: nd[] indices are compile-time constants -> registers.
    int hit_n = -1, hit_src = 0;
    #pragma unroll
    for (int n = NB - 1; n >= 0; --n) {
        const int off = (n == 0) ? 0 : nd[n - 1];
        const int k   = nd[n];
        if (hit_n < 0 && r >= off && r < off + k) {
            hit_n = n;
            hit_src = r - off;
        }
    }

    float val = 0.0f;
    if (hit_n >= 0) {
        const size_t base = (size_t)hit_n * N + hit_src;
        if (c == 0)      val = (float)hit_n;
        else if (c <= 4) val = boxes[base * 4 + (c - 1)];
        else if (c == 5) val = classes[base];
        else             val = scores[base];
    }
    out[t] = val;
}

extern "C" void kernel_launch(void* const* d_in, const int* in_sizes, int n_in,
                              void* d_out, int out_size) {
    const int4*  num_dets4 = (const int4*)d_in[0];
    const float* boxes     = (const float*)d_in[1];
    const float* scores    = (const float*)d_in[2];
    const float* classes   = (const float*)d_in[3];
    float*       out       = (float*)d_out;

    const int B = in_sizes[0];          // 8
    const int N = in_sizes[2] / B;      // 8192

    e2e_fixed_output_kernel<<<1, NTHREADS>>>(num_dets4, boxes, scores, classes, out, N);
}